// round 9
// baseline (speedup 1.0000x reference)
#include <cuda_runtime.h>
#include <cuda_fp16.h>

#define NN 100000
#define NE 1600000
#define CH 64
#define OUTC 32
#define NB 148
#define NT 1024
#define CHUNK 676                       // ceil(NN / NB)
#define NR (NE + 3 * NN + 64)

// ---------------- device scratch ----------------
__device__ int    g_deg[NN];
__device__ int    g_off[NN];
__device__ int    g_cur[NN];
__device__ float  g_dinv[NN];
__device__ int    g_bsums[NB];
__device__ __align__(16) int    g_r[NR];       // src rows, counting-sorted by target, 4-padded segs
__device__ __align__(16) __half g_t[NN * CH];  // dinv-scaled transformed features (fp16)
__device__ __align__(16) float  g_h[NN * CH];  // aggregated + relu (fp32)
__device__ unsigned g_cnt;
__device__ unsigned g_gen;                      // monotonic barrier generation

typedef unsigned long long u64;

__device__ __forceinline__ u64 pack2(float lo, float hi) {
    u64 r; asm("mov.b64 %0, {%1, %2};" : "=l"(r) : "f"(lo), "f"(hi)); return r;
}
__device__ __forceinline__ void unpack2(u64 v, float& lo, float& hi) {
    asm("mov.b64 {%0, %1}, %2;" : "=f"(lo), "=f"(hi) : "l"(v));
}
__device__ __forceinline__ void fma2(u64& acc, u64 a, u64 b) {
    asm("fma.rn.f32x2 %0, %1, %2, %0;" : "+l"(acc) : "l"(a), "l"(b));
}

// software grid barrier (all NB blocks co-resident)
__device__ __forceinline__ void gsync(unsigned target) {
    __threadfence();
    __syncthreads();
    if (threadIdx.x == 0) {
        if (atomicAdd(&g_cnt, 1u) == NB - 1) {
            atomicExch(&g_cnt, 0u);
            __threadfence();
            atomicExch(&g_gen, target);
        } else {
            while (atomicAdd(&g_gen, 0u) < target) { }
        }
    }
    __syncthreads();
}

// ---------------- CSR build: zero + count + scan + fill, one kernel ----------------
extern "C" __global__ void __launch_bounds__(NT, 1)
csr_mega(const int* __restrict__ ei) {
    __shared__ int s_wsum[32];
    __shared__ int s_prefix;
    __shared__ unsigned s_base;
    const int tid = threadIdx.x;
    const int bid = blockIdx.x;
    const int gt  = bid * NT + tid;
    const int GS  = NB * NT;

    if (tid == 0) s_base = atomicAdd(&g_gen, 0u);
    __syncthreads();
    const unsigned base = s_base;

    // P0: zero degrees
    for (int i = gt; i < NN; i += GS) g_deg[i] = 0;
    gsync(base + 1);

    // P1: count
    for (int e4 = gt; e4 < NE / 4; e4 += GS) {
        int4 c = *(const int4*)&ei[NE + e4 * 4];
        atomicAdd(&g_deg[c.x], 1);
        atomicAdd(&g_deg[c.y], 1);
        atomicAdd(&g_deg[c.z], 1);
        atomicAdd(&g_deg[c.w], 1);
    }
    gsync(base + 2);

    // P2: per-block scan of padded degrees over contiguous chunk
    int node = bid * CHUNK + tid;
    int deg  = (tid < CHUNK && node < NN) ? g_deg[node] : 0;
    int v    = (deg + 3) & ~3;
    {
        int lane = tid & 31, wid = tid >> 5;
        int s = v;
#pragma unroll
        for (int d = 1; d < 32; d <<= 1) {
            int n = __shfl_up_sync(0xffffffffu, s, d);
            if (lane >= d) s += n;
        }
        if (lane == 31) s_wsum[wid] = s;
        __syncthreads();
        if (wid == 0) {
            int t = s_wsum[lane];
#pragma unroll
            for (int d = 1; d < 32; d <<= 1) {
                int n = __shfl_up_sync(0xffffffffu, t, d);
                if (lane >= d) t += n;
            }
            s_wsum[lane] = t;
        }
        __syncthreads();
        int warpExcl = (wid > 0) ? s_wsum[wid - 1] : 0;
        if (tid < CHUNK && node < NN) g_off[node] = warpExcl + (s - v);
        if (tid == 0) g_bsums[bid] = s_wsum[31];
        gsync(base + 3);

        // P3: block base prefix + finalize offsets/cursors/dinv
        if (tid < 32) {
            int sum = 0;
            for (int j = tid; j < bid; j += 32) sum += g_bsums[j];
#pragma unroll
            for (int d = 16; d; d >>= 1) sum += __shfl_xor_sync(0xffffffffu, sum, d);
            if (tid == 0) s_prefix = sum;
        }
        __syncthreads();
        if (tid < CHUNK && node < NN) {
            int o = g_off[node] + s_prefix;
            g_off[node] = o;
            g_cur[node] = o;
            g_dinv[node] = rsqrtf((float)(deg + 1));
        }
    }
    gsync(base + 4);

    // P4: fill
    for (int e4 = gt; e4 < NE / 4; e4 += GS) {
        int4 r = *(const int4*)&ei[e4 * 4];
        int4 c = *(const int4*)&ei[NE + e4 * 4];
        g_r[atomicAdd(&g_cur[c.x], 1)] = r.x;
        g_r[atomicAdd(&g_cur[c.y], 1)] = r.y;
        g_r[atomicAdd(&g_cur[c.z], 1)] = r.z;
        g_r[atomicAdd(&g_cur[c.w], 1)] = r.w;
    }
}

// profiler-slot spacer
__global__ void k_dummy() { }

// ---------------- GEMM: out[N, COUT] = X[N, 64] @ W[64, COUT] (+bias) (*dinv[row]) ----
template<int COUT, bool BIAS, bool SRC_H, bool DST_PARAM, bool SCALE>
__global__ void k_gemm(const float* __restrict__ Xparam, const float* __restrict__ W,
                       const float* __restrict__ bias, float* __restrict__ outparam) {
    const float* X = SRC_H ? (const float*)g_h : Xparam;

    constexpr int G   = COUT / 8;
    constexpr int TR  = 256 / G;
    constexpr int RPB = TR * 2;
    constexpr int XS  = 65;
    __shared__ __align__(16) float Wsh[CH * COUT];
    __shared__ float Xsh[RPB][XS];
    int tid = threadIdx.x;

    for (int i = tid; i < CH * COUT; i += 256) Wsh[i] = W[i];

    int row0 = blockIdx.x * RPB;
    {
        int k = tid & 63;
        for (int r = tid >> 6; r < RPB; r += 4) {
            int row = row0 + r;
            Xsh[r][k] = (row < NN) ? X[row * CH + k] : 0.f;
        }
    }
    __syncthreads();

    int cg = tid & (G - 1);
    int rt = tid / G;
    int r0 = rt * 2, r1 = r0 + 1;
    u64 acc0[4] = {0, 0, 0, 0};
    u64 acc1[4] = {0, 0, 0, 0};
    const float* wp = &Wsh[cg * 8];

#pragma unroll 4
    for (int k = 0; k < CH; k++) {
        float x0 = Xsh[r0][k];
        float x1 = Xsh[r1][k];
        u64 xp0 = pack2(x0, x0);
        u64 xp1 = pack2(x1, x1);
        ulonglong2 wa = *(const ulonglong2*)(wp + k * COUT);
        ulonglong2 wb = *(const ulonglong2*)(wp + k * COUT + 4);
        fma2(acc0[0], xp0, wa.x); fma2(acc0[1], xp0, wa.y);
        fma2(acc0[2], xp0, wb.x); fma2(acc0[3], xp0, wb.y);
        fma2(acc1[0], xp1, wa.x); fma2(acc1[1], xp1, wa.y);
        fma2(acc1[2], xp1, wb.x); fma2(acc1[3], xp1, wb.y);
    }

    float4 bb0 = make_float4(0, 0, 0, 0), bb1 = make_float4(0, 0, 0, 0);
    if (BIAS) {
        bb0 = *(const float4*)&bias[cg * 8];
        bb1 = *(const float4*)&bias[cg * 8 + 4];
    }
#pragma unroll
    for (int p = 0; p < 2; p++) {
        int row = row0 + (p == 0 ? r0 : r1);
        if (row < NN) {
            u64* acc = (p == 0) ? acc0 : acc1;
            float4 f0, f1;
            unpack2(acc[0], f0.x, f0.y); unpack2(acc[1], f0.z, f0.w);
            unpack2(acc[2], f1.x, f1.y); unpack2(acc[3], f1.z, f1.w);
            if (SCALE) {
                float s = g_dinv[row];
                f0.x *= s; f0.y *= s; f0.z *= s; f0.w *= s;
                f1.x *= s; f1.y *= s; f1.z *= s; f1.w *= s;
            }
            if (BIAS) {
                f0.x += bb0.x; f0.y += bb0.y; f0.z += bb0.z; f0.w += bb0.w;
                f1.x += bb1.x; f1.y += bb1.y; f1.z += bb1.z; f1.w += bb1.w;
            }
            if (DST_PARAM) {
                *(float4*)&outparam[row * COUT + cg * 8]     = f0;
                *(float4*)&outparam[row * COUT + cg * 8 + 4] = f1;
            } else {
                __half2 hv[4];
                hv[0] = __floats2half2_rn(f0.x, f0.y);
                hv[1] = __floats2half2_rn(f0.z, f0.w);
                hv[2] = __floats2half2_rn(f1.x, f1.y);
                hv[3] = __floats2half2_rn(f1.z, f1.w);
                *(uint4*)&g_t[row * COUT + cg * 8] = *(uint4*)hv;
            }
        }
    }
}

// ---------------- Aggregation: one warp per node; index prefetch; fp16 gathers ------
// g_h[t] = relu( dinv[t] * (sum_nbr g_t[r] + g_t[t]) + bias )
__global__ void __launch_bounds__(256, 5) k_agg(const float* __restrict__ bias) {
    int gw   = (blockIdx.x * blockDim.x + threadIdx.x) >> 5;
    int lane = threadIdx.x & 31;
    if (gw >= NN) return;

    int start = g_off[gw];          // 4-aligned
    int cnt   = g_deg[gw];
    int endt  = start + cnt;
    const __half2* hp = (const __half2*)g_t;

    float ax = 0.f, ay = 0.f;
    int4 a = make_int4(0, 0, 0, 0), b = a;
    if (start < endt) {
        a = *(const int4*)&g_r[start];
        b = *(const int4*)&g_r[start + 4];     // within padded slack
    }
    for (int e = start; e < endt; e += 8) {
        int4 ca = a, cb = b;
        int en = e + 8;
        if (en < endt) {                        // prefetch next iteration's indices
            a = *(const int4*)&g_r[en];
            b = *(const int4*)&g_r[en + 4];
        }
        int rem = endt - e;
        {            float2 v = __half22float2(hp[ca.x * 32 + lane]); ax += v.x; ay += v.y; }
        if (rem > 1) { float2 v = __half22float2(hp[ca.y * 32 + lane]); ax += v.x; ay += v.y; }
        if (rem > 2) { float2 v = __half22float2(hp[ca.z * 32 + lane]); ax += v.x; ay += v.y; }
        if (rem > 3) { float2 v = __half22float2(hp[ca.w * 32 + lane]); ax += v.x; ay += v.y; }
        if (rem > 4) { float2 v = __half22float2(hp[cb.x * 32 + lane]); ax += v.x; ay += v.y; }
        if (rem > 5) { float2 v = __half22float2(hp[cb.y * 32 + lane]); ax += v.x; ay += v.y; }
        if (rem > 6) { float2 v = __half22float2(hp[cb.z * 32 + lane]); ax += v.x; ay += v.y; }
        if (rem > 7) { float2 v = __half22float2(hp[cb.w * 32 + lane]); ax += v.x; ay += v.y; }
    }

    float dt = g_dinv[gw];
    float2 sv = __half22float2(hp[gw * 32 + lane]);
    float2 bb = ((const float2*)bias)[lane];
    float ox = fmaf(dt, ax + sv.x, bb.x);
    float oy = fmaf(dt, ay + sv.y, bb.y);
    ((float2*)g_h)[gw * 32 + lane] = make_float2(fmaxf(ox, 0.f), fmaxf(oy, 0.f));
}

// ---------------- launch ----------------
extern "C" void kernel_launch(void* const* d_in, const int* in_sizes, int n_in,
                              void* d_out, int out_size) {
    const float* x    = (const float*)d_in[0];
    const int*   ei   = (const int*)d_in[1];
    const float* W1   = (const float*)d_in[2];
    const float* b1   = (const float*)d_in[3];
    const float* W2   = (const float*)d_in[4];
    const float* b2   = (const float*)d_in[5];
    const float* Wlin = (const float*)d_in[6];
    const float* blin = (const float*)d_in[7];
    float* out = (float*)d_out;

    // 1: CSR build (fused, grid-synced)
    csr_mega<<<NB, NT>>>(ei);
    // 2: layer-1 GEMM: x -> g_t (fp16, dinv-scaled)
    k_gemm<64, false, false, false, true><<<(NN + 63) / 64, 256>>>(x, W1, nullptr, nullptr);
    // 3: spacer so launch #4 (profiled slot) is agg1
    k_dummy<<<1, 32>>>();
    // 4: agg layer 1  <- PROFILED
    k_agg<<<(NN + 7) / 8, 256>>>(b1);
    // 5: layer-2 GEMM: g_h -> g_t (fp16, dinv-scaled)
    k_gemm<64, false, true, false, true><<<(NN + 63) / 64, 256>>>(nullptr, W2, nullptr, nullptr);
    // 6: agg layer 2
    k_agg<<<(NN + 7) / 8, 256>>>(b2);
    // 7: linear head -> out (fp32 + bias)
    k_gemm<32, true, true, true, false><<<(NN + 127) / 128, 256>>>(nullptr, Wlin, blin, out);
}

// round 10
// speedup vs baseline: 1.1590x; 1.1590x over previous
#include <cuda_runtime.h>
#include <cuda_fp16.h>

#define NN 100000
#define NE 1600000
#define CH 64
#define OUTC 32
#define NB 148
#define NT 1024
#define CHUNK 676                       // ceil(NN / NB)
#define NR (NE + 8 * NN + 64)           // 8-padded segment capacity

// ---------------- device scratch ----------------
__device__ int    g_deg[NN];
__device__ int    g_off[NN];
__device__ int    g_cur[NN];
__device__ float  g_dinv[NN];
__device__ int    g_bsums[NB];
__device__ __align__(16) int    g_r[NR];            // src rows sorted by target; pads -> row NN
__device__ __align__(16) __half g_t[(NN + 1) * CH]; // fp16 features; row NN is permanent zeros
__device__ __align__(16) float  g_h[NN * CH];       // aggregated + relu (fp32)
__device__ unsigned g_cnt;
__device__ unsigned g_gen;                           // monotonic barrier generation

typedef unsigned long long u64;

__device__ __forceinline__ u64 pack2(float lo, float hi) {
    u64 r; asm("mov.b64 %0, {%1, %2};" : "=l"(r) : "f"(lo), "f"(hi)); return r;
}
__device__ __forceinline__ void unpack2(u64 v, float& lo, float& hi) {
    asm("mov.b64 {%0, %1}, %2;" : "=f"(lo), "=f"(hi) : "l"(v));
}
__device__ __forceinline__ void fma2(u64& acc, u64 a, u64 b) {
    asm("fma.rn.f32x2 %0, %1, %2, %0;" : "+l"(acc) : "l"(a), "l"(b));
}

// software grid barrier (all NB blocks co-resident)
__device__ __forceinline__ void gsync(unsigned target) {
    __threadfence();
    __syncthreads();
    if (threadIdx.x == 0) {
        if (atomicAdd(&g_cnt, 1u) == NB - 1) {
            atomicExch(&g_cnt, 0u);
            __threadfence();
            atomicExch(&g_gen, target);
        } else {
            while (atomicAdd(&g_gen, 0u) < target) { }
        }
    }
    __syncthreads();
}

// ---------------- CSR build: zero + count + scan(+pad) + fill, one kernel ----------------
extern "C" __global__ void __launch_bounds__(NT, 1)
csr_mega(const int* __restrict__ ei) {
    __shared__ int s_wsum[32];
    __shared__ int s_prefix;
    __shared__ unsigned s_base;
    const int tid = threadIdx.x;
    const int bid = blockIdx.x;
    const int gt  = bid * NT + tid;
    const int GS  = NB * NT;

    if (tid == 0) s_base = atomicAdd(&g_gen, 0u);
    __syncthreads();
    const unsigned base = s_base;

    // P0: zero degrees
    for (int i = gt; i < NN; i += GS) g_deg[i] = 0;
    gsync(base + 1);

    // P1: count
    for (int e4 = gt; e4 < NE / 4; e4 += GS) {
        int4 c = *(const int4*)&ei[NE + e4 * 4];
        atomicAdd(&g_deg[c.x], 1);
        atomicAdd(&g_deg[c.y], 1);
        atomicAdd(&g_deg[c.z], 1);
        atomicAdd(&g_deg[c.w], 1);
    }
    gsync(base + 2);

    // P2: per-block scan of 8-padded degrees over contiguous chunk
    int node = bid * CHUNK + tid;
    int deg  = (tid < CHUNK && node < NN) ? g_deg[node] : 0;
    int v    = (deg + 7) & ~7;
    {
        int lane = tid & 31, wid = tid >> 5;
        int s = v;
#pragma unroll
        for (int d = 1; d < 32; d <<= 1) {
            int n = __shfl_up_sync(0xffffffffu, s, d);
            if (lane >= d) s += n;
        }
        if (lane == 31) s_wsum[wid] = s;
        __syncthreads();
        if (wid == 0) {
            int t = s_wsum[lane];
#pragma unroll
            for (int d = 1; d < 32; d <<= 1) {
                int n = __shfl_up_sync(0xffffffffu, t, d);
                if (lane >= d) t += n;
            }
            s_wsum[lane] = t;
        }
        __syncthreads();
        int warpExcl = (wid > 0) ? s_wsum[wid - 1] : 0;
        if (tid < CHUNK && node < NN) g_off[node] = warpExcl + (s - v);
        if (tid == 0) g_bsums[bid] = s_wsum[31];
        gsync(base + 3);

        // P3: block base prefix + finalize offsets/cursors/dinv + write pad slots
        if (tid < 32) {
            int sum = 0;
            for (int j = tid; j < bid; j += 32) sum += g_bsums[j];
#pragma unroll
            for (int d = 16; d; d >>= 1) sum += __shfl_xor_sync(0xffffffffu, sum, d);
            if (tid == 0) s_prefix = sum;
        }
        __syncthreads();
        if (tid < CHUNK && node < NN) {
            int o = g_off[node] + s_prefix;
            g_off[node] = o;
            g_cur[node] = o;
            g_dinv[node] = rsqrtf((float)(deg + 1));
            for (int j = deg; j < v; j++) g_r[o + j] = NN;   // pad -> zero row
        }
    }
    gsync(base + 4);

    // P4: fill real edges
    for (int e4 = gt; e4 < NE / 4; e4 += GS) {
        int4 r = *(const int4*)&ei[e4 * 4];
        int4 c = *(const int4*)&ei[NE + e4 * 4];
        g_r[atomicAdd(&g_cur[c.x], 1)] = r.x;
        g_r[atomicAdd(&g_cur[c.y], 1)] = r.y;
        g_r[atomicAdd(&g_cur[c.z], 1)] = r.z;
        g_r[atomicAdd(&g_cur[c.w], 1)] = r.w;
    }
}

// ---------------- GEMM: out[N, COUT] = X[N, 64] @ W[64, COUT] (+bias) (*dinv[row]) ----
template<int COUT, bool BIAS, bool SRC_H, bool DST_PARAM, bool SCALE>
__global__ void k_gemm(const float* __restrict__ Xparam, const float* __restrict__ W,
                       const float* __restrict__ bias, float* __restrict__ outparam) {
    const float* X = SRC_H ? (const float*)g_h : Xparam;

    constexpr int G   = COUT / 8;
    constexpr int TR  = 256 / G;
    constexpr int RPB = TR * 2;
    constexpr int XS  = 65;
    __shared__ __align__(16) float Wsh[CH * COUT];
    __shared__ float Xsh[RPB][XS];
    int tid = threadIdx.x;

    for (int i = tid; i < CH * COUT; i += 256) Wsh[i] = W[i];

    int row0 = blockIdx.x * RPB;
    {
        int k = tid & 63;
        for (int r = tid >> 6; r < RPB; r += 4) {
            int row = row0 + r;
            Xsh[r][k] = (row < NN) ? X[row * CH + k] : 0.f;
        }
    }
    __syncthreads();

    int cg = tid & (G - 1);
    int rt = tid / G;
    int r0 = rt * 2, r1 = r0 + 1;
    u64 acc0[4] = {0, 0, 0, 0};
    u64 acc1[4] = {0, 0, 0, 0};
    const float* wp = &Wsh[cg * 8];

#pragma unroll 4
    for (int k = 0; k < CH; k++) {
        float x0 = Xsh[r0][k];
        float x1 = Xsh[r1][k];
        u64 xp0 = pack2(x0, x0);
        u64 xp1 = pack2(x1, x1);
        ulonglong2 wa = *(const ulonglong2*)(wp + k * COUT);
        ulonglong2 wb = *(const ulonglong2*)(wp + k * COUT + 4);
        fma2(acc0[0], xp0, wa.x); fma2(acc0[1], xp0, wa.y);
        fma2(acc0[2], xp0, wb.x); fma2(acc0[3], xp0, wb.y);
        fma2(acc1[0], xp1, wa.x); fma2(acc1[1], xp1, wa.y);
        fma2(acc1[2], xp1, wb.x); fma2(acc1[3], xp1, wb.y);
    }

    float4 bb0 = make_float4(0, 0, 0, 0), bb1 = make_float4(0, 0, 0, 0);
    if (BIAS) {
        bb0 = *(const float4*)&bias[cg * 8];
        bb1 = *(const float4*)&bias[cg * 8 + 4];
    }
#pragma unroll
    for (int p = 0; p < 2; p++) {
        int row = row0 + (p == 0 ? r0 : r1);
        if (row < NN) {
            u64* acc = (p == 0) ? acc0 : acc1;
            float4 f0, f1;
            unpack2(acc[0], f0.x, f0.y); unpack2(acc[1], f0.z, f0.w);
            unpack2(acc[2], f1.x, f1.y); unpack2(acc[3], f1.z, f1.w);
            if (SCALE) {
                float s = g_dinv[row];
                f0.x *= s; f0.y *= s; f0.z *= s; f0.w *= s;
                f1.x *= s; f1.y *= s; f1.z *= s; f1.w *= s;
            }
            if (BIAS) {
                f0.x += bb0.x; f0.y += bb0.y; f0.z += bb0.z; f0.w += bb0.w;
                f1.x += bb1.x; f1.y += bb1.y; f1.z += bb1.z; f1.w += bb1.w;
            }
            if (DST_PARAM) {
                *(float4*)&outparam[row * COUT + cg * 8]     = f0;
                *(float4*)&outparam[row * COUT + cg * 8 + 4] = f1;
            } else {
                __half2 hv[4];
                hv[0] = __floats2half2_rn(f0.x, f0.y);
                hv[1] = __floats2half2_rn(f0.z, f0.w);
                hv[2] = __floats2half2_rn(f1.x, f1.y);
                hv[3] = __floats2half2_rn(f1.z, f1.w);
                *(uint4*)&g_t[row * COUT + cg * 8] = *(uint4*)hv;
            }
        }
    }
}

// ---------------- Aggregation: one warp per node; branch-free 8-wide pipelined gathers
// g_h[t] = relu( dinv[t] * (sum_nbr g_t[r] + g_t[t]) + bias )
__global__ void k_agg(const float* __restrict__ bias) {
    int gw   = (blockIdx.x * blockDim.x + threadIdx.x) >> 5;
    int lane = threadIdx.x & 31;
    if (gw >= NN) return;

    int start = g_off[gw];
    int pcnt  = (g_deg[gw] + 7) & ~7;       // 8-padded; pads hit zero row
    int endp  = start + pcnt;
    const __half2* hp = (const __half2*)g_t;

    float2 s0 = make_float2(0.f, 0.f), s1 = s0, s2 = s0, s3 = s0;

    if (pcnt > 0) {
        int4 ia = *(const int4*)&g_r[start];
        int4 ib = *(const int4*)&g_r[start + 4];
        __half2 g0 = hp[ia.x * 32 + lane], g1 = hp[ia.y * 32 + lane];
        __half2 g2 = hp[ia.z * 32 + lane], g3 = hp[ia.w * 32 + lane];
        __half2 g4 = hp[ib.x * 32 + lane], g5 = hp[ib.y * 32 + lane];
        __half2 g6 = hp[ib.z * 32 + lane], g7 = hp[ib.w * 32 + lane];

        for (int e = start + 8; e < endp; e += 8) {
            int4 na = *(const int4*)&g_r[e];
            int4 nb = *(const int4*)&g_r[e + 4];
            __half2 n0 = hp[na.x * 32 + lane], n1 = hp[na.y * 32 + lane];
            __half2 n2 = hp[na.z * 32 + lane], n3 = hp[na.w * 32 + lane];
            __half2 n4 = hp[nb.x * 32 + lane], n5 = hp[nb.y * 32 + lane];
            __half2 n6 = hp[nb.z * 32 + lane], n7 = hp[nb.w * 32 + lane];
            { float2 v = __half22float2(g0); s0.x += v.x; s0.y += v.y; }
            { float2 v = __half22float2(g1); s1.x += v.x; s1.y += v.y; }
            { float2 v = __half22float2(g2); s2.x += v.x; s2.y += v.y; }
            { float2 v = __half22float2(g3); s3.x += v.x; s3.y += v.y; }
            { float2 v = __half22float2(g4); s0.x += v.x; s0.y += v.y; }
            { float2 v = __half22float2(g5); s1.x += v.x; s1.y += v.y; }
            { float2 v = __half22float2(g6); s2.x += v.x; s2.y += v.y; }
            { float2 v = __half22float2(g7); s3.x += v.x; s3.y += v.y; }
            g0 = n0; g1 = n1; g2 = n2; g3 = n3;
            g4 = n4; g5 = n5; g6 = n6; g7 = n7;
        }
        { float2 v = __half22float2(g0); s0.x += v.x; s0.y += v.y; }
        { float2 v = __half22float2(g1); s1.x += v.x; s1.y += v.y; }
        { float2 v = __half22float2(g2); s2.x += v.x; s2.y += v.y; }
        { float2 v = __half22float2(g3); s3.x += v.x; s3.y += v.y; }
        { float2 v = __half22float2(g4); s0.x += v.x; s0.y += v.y; }
        { float2 v = __half22float2(g5); s1.x += v.x; s1.y += v.y; }
        { float2 v = __half22float2(g6); s2.x += v.x; s2.y += v.y; }
        { float2 v = __half22float2(g7); s3.x += v.x; s3.y += v.y; }
    }

    float ax = (s0.x + s1.x) + (s2.x + s3.x);
    float ay = (s0.y + s1.y) + (s2.y + s3.y);

    float dt = g_dinv[gw];
    float2 sv = __half22float2(hp[gw * 32 + lane]);
    float2 bb = ((const float2*)bias)[lane];
    float ox = fmaf(dt, ax + sv.x, bb.x);
    float oy = fmaf(dt, ay + sv.y, bb.y);
    ((float2*)g_h)[gw * 32 + lane] = make_float2(fmaxf(ox, 0.f), fmaxf(oy, 0.f));
}

// ---------------- launch ----------------
extern "C" void kernel_launch(void* const* d_in, const int* in_sizes, int n_in,
                              void* d_out, int out_size) {
    const float* x    = (const float*)d_in[0];
    const int*   ei   = (const int*)d_in[1];
    const float* W1   = (const float*)d_in[2];
    const float* b1   = (const float*)d_in[3];
    const float* W2   = (const float*)d_in[4];
    const float* b2   = (const float*)d_in[5];
    const float* Wlin = (const float*)d_in[6];
    const float* blin = (const float*)d_in[7];
    float* out = (float*)d_out;

    // 1: CSR build (fused, grid-synced)
    csr_mega<<<NB, NT>>>(ei);
    // 2: layer-1 GEMM: x -> g_t (fp16, dinv-scaled)
    k_gemm<64, false, false, false, true><<<(NN + 63) / 64, 256>>>(x, W1, nullptr, nullptr);
    // 3: agg layer 1
    k_agg<<<(NN + 7) / 8, 256>>>(b1);
    // 4: layer-2 GEMM: g_h -> g_t (fp16, dinv-scaled)
    k_gemm<64, false, true, false, true><<<(NN + 63) / 64, 256>>>(nullptr, W2, nullptr, nullptr);
    // 5: agg layer 2
    k_agg<<<(NN + 7) / 8, 256>>>(b2);
    // 6: linear head -> out (fp32 + bias)
    k_gemm<32, true, true, true, false><<<(NN + 127) / 128, 256>>>(nullptr, Wlin, blin, out);
}

// round 11
// speedup vs baseline: 1.8445x; 1.5914x over previous
#include <cuda_runtime.h>
#include <cuda_fp16.h>
#include <mma.h>

using namespace nvcuda;

#define NN 100000
#define NE 1600000
#define CH 64
#define OUTC 32
#define NB 148
#define NT 1024
#define CHUNK 676                       // ceil(NN / NB)
#define NR (NE + 8 * NN + 64)           // 8-padded segment capacity
#define NROWPAD 160                     // GEMM tile overhang padding (rows)

// ---------------- device scratch ----------------
__device__ int    g_deg[NN];
__device__ int    g_off[NN];
__device__ int    g_cur[NN];
__device__ float  g_dinv[NN];
__device__ int    g_bsums[NB];
__device__ __align__(16) int    g_r[NR];                  // src rows sorted by target; pads -> row NN
__device__ __align__(16) __half g_a[(NN + NROWPAD) * CH]; // GEMM input (fp16, dinv-scaled as needed)
__device__ __align__(16) __half g_t[(NN + 1) * CH];       // GEMM output / agg gather src; row NN = zeros
__device__ unsigned g_cnt;
__device__ unsigned g_gen;                                 // monotonic barrier generation

// software grid barrier (all NB blocks co-resident)
__device__ __forceinline__ void gsync(unsigned target) {
    __threadfence();
    __syncthreads();
    if (threadIdx.x == 0) {
        if (atomicAdd(&g_cnt, 1u) == NB - 1) {
            atomicExch(&g_cnt, 0u);
            __threadfence();
            atomicExch(&g_gen, target);
        } else {
            while (atomicAdd(&g_gen, 0u) < target) { }
        }
    }
    __syncthreads();
}

// ---------------- CSR build + input conversion: one grid-synced kernel ----------------
extern "C" __global__ void __launch_bounds__(NT, 1)
csr_mega(const int* __restrict__ ei, const float* __restrict__ x) {
    __shared__ int s_wsum[32];
    __shared__ int s_prefix;
    __shared__ unsigned s_base;
    const int tid = threadIdx.x;
    const int bid = blockIdx.x;
    const int gt  = bid * NT + tid;
    const int GS  = NB * NT;

    if (tid == 0) s_base = atomicAdd(&g_gen, 0u);
    __syncthreads();
    const unsigned base = s_base;

    // P0: zero degrees
    for (int i = gt; i < NN; i += GS) g_deg[i] = 0;
    gsync(base + 1);

    // P1: count
    for (int e4 = gt; e4 < NE / 4; e4 += GS) {
        int4 c = *(const int4*)&ei[NE + e4 * 4];
        atomicAdd(&g_deg[c.x], 1);
        atomicAdd(&g_deg[c.y], 1);
        atomicAdd(&g_deg[c.z], 1);
        atomicAdd(&g_deg[c.w], 1);
    }
    gsync(base + 2);

    // P2: per-block scan of 8-padded degrees over contiguous chunk
    int node = bid * CHUNK + tid;
    int deg  = (tid < CHUNK && node < NN) ? g_deg[node] : 0;
    int v    = (deg + 7) & ~7;
    {
        int lane = tid & 31, wid = tid >> 5;
        int s = v;
#pragma unroll
        for (int d = 1; d < 32; d <<= 1) {
            int n = __shfl_up_sync(0xffffffffu, s, d);
            if (lane >= d) s += n;
        }
        if (lane == 31) s_wsum[wid] = s;
        __syncthreads();
        if (wid == 0) {
            int t = s_wsum[lane];
#pragma unroll
            for (int d = 1; d < 32; d <<= 1) {
                int n = __shfl_up_sync(0xffffffffu, t, d);
                if (lane >= d) t += n;
            }
            s_wsum[lane] = t;
        }
        __syncthreads();
        int warpExcl = (wid > 0) ? s_wsum[wid - 1] : 0;
        if (tid < CHUNK && node < NN) g_off[node] = warpExcl + (s - v);
        if (tid == 0) g_bsums[bid] = s_wsum[31];
        gsync(base + 3);

        // P3: block base prefix + finalize offsets/cursors/dinv + write pad slots
        if (tid < 32) {
            int sum = 0;
            for (int j = tid; j < bid; j += 32) sum += g_bsums[j];
#pragma unroll
            for (int d = 16; d; d >>= 1) sum += __shfl_xor_sync(0xffffffffu, sum, d);
            if (tid == 0) s_prefix = sum;
        }
        __syncthreads();
        if (tid < CHUNK && node < NN) {
            int o = g_off[node] + s_prefix;
            g_off[node] = o;
            g_cur[node] = o;
            g_dinv[node] = rsqrtf((float)(deg + 1));
            for (int j = deg; j < v; j++) g_r[o + j] = NN;   // pad -> zero row
        }
    }
    gsync(base + 4);

    // P4a: fill real edges
    for (int e4 = gt; e4 < NE / 4; e4 += GS) {
        int4 r = *(const int4*)&ei[e4 * 4];
        int4 c = *(const int4*)&ei[NE + e4 * 4];
        g_r[atomicAdd(&g_cur[c.x], 1)] = r.x;
        g_r[atomicAdd(&g_cur[c.y], 1)] = r.y;
        g_r[atomicAdd(&g_cur[c.z], 1)] = r.z;
        g_r[atomicAdd(&g_cur[c.w], 1)] = r.w;
    }
    // P4b: g_a = fp16(dinv ⊙ x)   (dinv visible since barrier base+4)
    {
        const float2* xp = (const float2*)x;
        __half2* ap = (__half2*)g_a;
        for (int i = gt; i < NN * 32; i += GS) {
            float s = g_dinv[i >> 5];
            float2 f = xp[i];
            ap[i] = __floats2half2_rn(f.x * s, f.y * s);
        }
    }
}

// ---------------- tensor-core GEMM: out[N, COUT] = g_a[N,64] @ W[64, COUT] ----------------
// block = 256 threads (8 warps), 128 rows/block. A staged in smem (ldm 72, conflict-free LDSM),
// W converted fp32->fp16 in-block. Epilogue: smem fp32 stage -> convert/store.
#define ALDM 72
template<int COUT, bool BIAS, bool HALFOUT>
__global__ void __launch_bounds__(256) k_wgemm(const float* __restrict__ W,
                                               const float* __restrict__ bias,
                                               float* __restrict__ outp) {
    __shared__ __align__(16) char buf[32768];
    __half* sA = (__half*)buf;                      // 128 x ALDM halves = 18432 B
    __half* sB = (__half*)(buf + 18432);            // 64 x ALDM halves  =  9216 B
    float*  sC = (float*)buf;                       // 128 x COUT fp32 (reused after sync)

    const int tid  = threadIdx.x;
    const int wid  = tid >> 5;
    const int lane = tid & 31;
    const int row0 = blockIdx.x * 128;

    // stage A: 128 rows x 64 halves, 8-half chunks
    {
        const uint4* src = (const uint4*)(g_a + (size_t)row0 * CH);
        for (int i = tid; i < 128 * 8; i += 256) {
            int r = i >> 3, c = i & 7;
            *(uint4*)(sA + r * ALDM + c * 8) = src[r * 8 + c];
        }
    }
    // stage B: convert W fp32 -> fp16
    for (int i = tid; i < CH * COUT; i += 256)
        sB[(i / COUT) * ALDM + (i % COUT)] = __float2half(W[i]);
    __syncthreads();

    wmma::fragment<wmma::accumulator, 16, 16, 16, float> acc[COUT / 16];
#pragma unroll
    for (int j = 0; j < COUT / 16; j++) wmma::fill_fragment(acc[j], 0.f);

#pragma unroll
    for (int k = 0; k < 4; k++) {
        wmma::fragment<wmma::matrix_a, 16, 16, 16, __half, wmma::row_major> af;
        wmma::load_matrix_sync(af, sA + wid * 16 * ALDM + k * 16, ALDM);
#pragma unroll
        for (int j = 0; j < COUT / 16; j++) {
            wmma::fragment<wmma::matrix_b, 16, 16, 16, __half, wmma::row_major> bf;
            wmma::load_matrix_sync(bf, sB + k * 16 * ALDM + j * 16, ALDM);
            wmma::mma_sync(acc[j], af, bf, acc[j]);
        }
    }
    __syncthreads();   // all A/B smem reads done; reuse buf as sC

#pragma unroll
    for (int j = 0; j < COUT / 16; j++)
        wmma::store_matrix_sync(sC + wid * 16 * COUT + j * 16, acc[j], COUT, wmma::mem_row_major);
    __syncwarp();

    if (HALFOUT) {
        // COUT=64: 2 lanes per row, 32 floats each -> 16 half2
        int r = wid * 16 + (lane >> 1);
        int off = (lane & 1) * 32;
        int grow = row0 + r;
        if (grow < NN) {
            const float* src = sC + r * COUT + off;
            __half2 hv[16];
#pragma unroll
            for (int j = 0; j < 16; j++) hv[j] = __floats2half2_rn(src[2 * j], src[2 * j + 1]);
            uint4* dst = (uint4*)(g_t + (size_t)grow * COUT + off);
#pragma unroll
            for (int j = 0; j < 4; j++) dst[j] = ((uint4*)hv)[j];
        }
    } else {
        // COUT=32: fp32 out (+bias); 2 lanes per row, 16 floats each
        int r = wid * 16 + (lane >> 1);
        int off = (lane & 1) * 16;
        int grow = row0 + r;
        if (grow < NN) {
#pragma unroll
            for (int j = 0; j < 4; j++) {
                float4 v = *(const float4*)(sC + r * COUT + off + j * 4);
                if (BIAS) {
                    float4 b = *(const float4*)(bias + off + j * 4);
                    v.x += b.x; v.y += b.y; v.z += b.z; v.w += b.w;
                }
                *(float4*)(outp + (size_t)grow * COUT + off + j * 4) = v;
            }
        }
    }
}

// ---------------- Aggregation: one warp per node; branch-free 8-wide pipelined gathers
// out = relu( dinv[t]*(sum_nbr g_t[r] + g_t[t]) + bias );  optionally *dinv[t] (next-layer input)
template<bool SCALE_OUT>
__global__ void k_agg(const float* __restrict__ bias) {
    int gw   = (blockIdx.x * blockDim.x + threadIdx.x) >> 5;
    int lane = threadIdx.x & 31;
    if (gw >= NN) return;

    int start = g_off[gw];
    int pcnt  = (g_deg[gw] + 7) & ~7;       // 8-padded; pads hit zero row
    int endp  = start + pcnt;
    const __half2* hp = (const __half2*)g_t;

    float2 s0 = make_float2(0.f, 0.f), s1 = s0, s2 = s0, s3 = s0;

    if (pcnt > 0) {
        int4 ia = *(const int4*)&g_r[start];
        int4 ib = *(const int4*)&g_r[start + 4];
        __half2 g0 = hp[ia.x * 32 + lane], g1 = hp[ia.y * 32 + lane];
        __half2 g2 = hp[ia.z * 32 + lane], g3 = hp[ia.w * 32 + lane];
        __half2 g4 = hp[ib.x * 32 + lane], g5 = hp[ib.y * 32 + lane];
        __half2 g6 = hp[ib.z * 32 + lane], g7 = hp[ib.w * 32 + lane];

        for (int e = start + 8; e < endp; e += 8) {
            int4 na = *(const int4*)&g_r[e];
            int4 nb = *(const int4*)&g_r[e + 4];
            __half2 n0 = hp[na.x * 32 + lane], n1 = hp[na.y * 32 + lane];
            __half2 n2 = hp[na.z * 32 + lane], n3 = hp[na.w * 32 + lane];
            __half2 n4 = hp[nb.x * 32 + lane], n5 = hp[nb.y * 32 + lane];
            __half2 n6 = hp[nb.z * 32 + lane], n7 = hp[nb.w * 32 + lane];
            { float2 v = __half22float2(g0); s0.x += v.x; s0.y += v.y; }
            { float2 v = __half22float2(g1); s1.x += v.x; s1.y += v.y; }
            { float2 v = __half22float2(g2); s2.x += v.x; s2.y += v.y; }
            { float2 v = __half22float2(g3); s3.x += v.x; s3.y += v.y; }
            { float2 v = __half22float2(g4); s0.x += v.x; s0.y += v.y; }
            { float2 v = __half22float2(g5); s1.x += v.x; s1.y += v.y; }
            { float2 v = __half22float2(g6); s2.x += v.x; s2.y += v.y; }
            { float2 v = __half22float2(g7); s3.x += v.x; s3.y += v.y; }
            g0 = n0; g1 = n1; g2 = n2; g3 = n3;
            g4 = n4; g5 = n5; g6 = n6; g7 = n7;
        }
        { float2 v = __half22float2(g0); s0.x += v.x; s0.y += v.y; }
        { float2 v = __half22float2(g1); s1.x += v.x; s1.y += v.y; }
        { float2 v = __half22float2(g2); s2.x += v.x; s2.y += v.y; }
        { float2 v = __half22float2(g3); s3.x += v.x; s3.y += v.y; }
        { float2 v = __half22float2(g4); s0.x += v.x; s0.y += v.y; }
        { float2 v = __half22float2(g5); s1.x += v.x; s1.y += v.y; }
        { float2 v = __half22float2(g6); s2.x += v.x; s2.y += v.y; }
        { float2 v = __half22float2(g7); s3.x += v.x; s3.y += v.y; }
    }

    float ax = (s0.x + s1.x) + (s2.x + s3.x);
    float ay = (s0.y + s1.y) + (s2.y + s3.y);

    float dt = g_dinv[gw];
    float2 sv = __half22float2(hp[gw * 32 + lane]);
    float2 bb = ((const float2*)bias)[lane];
    float ox = fmaxf(fmaf(dt, ax + sv.x, bb.x), 0.f);
    float oy = fmaxf(fmaf(dt, ay + sv.y, bb.y), 0.f);
    if (SCALE_OUT) { ox *= dt; oy *= dt; }
    ((__half2*)g_a)[gw * 32 + lane] = __floats2half2_rn(ox, oy);
}

// ---------------- launch ----------------
extern "C" void kernel_launch(void* const* d_in, const int* in_sizes, int n_in,
                              void* d_out, int out_size) {
    const float* x    = (const float*)d_in[0];
    const int*   ei   = (const int*)d_in[1];
    const float* W1   = (const float*)d_in[2];
    const float* b1   = (const float*)d_in[3];
    const float* W2   = (const float*)d_in[4];
    const float* b2   = (const float*)d_in[5];
    const float* Wlin = (const float*)d_in[6];
    const float* blin = (const float*)d_in[7];
    float* out = (float*)d_out;

    const int GGRID = (NN + 127) / 128;   // 782

    // 1: CSR build + g_a = fp16(dinv⊙x)
    csr_mega<<<NB, NT>>>(ei, x);
    // 2: GEMM1 (tensor cores): g_a -> g_t
    k_wgemm<64, false, true><<<GGRID, 256>>>(W1, nullptr, nullptr);
    // 3: agg layer 1 -> g_a (dinv-scaled fp16, ready for GEMM2)
    k_agg<true><<<(NN + 7) / 8, 256>>>(b1);
    // 4: GEMM2 (tensor cores): g_a -> g_t
    k_wgemm<64, false, true><<<GGRID, 256>>>(W2, nullptr, nullptr);
    // 5: agg layer 2 -> g_a (unscaled fp16 H2)
    k_agg<false><<<(NN + 7) / 8, 256>>>(b2);
    // 6: linear head (tensor cores): g_a -> out (fp32 + bias)
    k_wgemm<32, true, false><<<GGRID, 256>>>(Wlin, blin, out);
}